// round 2
// baseline (speedup 1.0000x reference)
#include <cuda_runtime.h>
#include <float.h>

// Problem constants (fixed shapes per reference)
#define B_DIM 4
#define H_DIM 16
#define L_DIM 2048
#define D_DIM 64
#define TOPK  128
#define SCALE 0.125f      // D^-0.5 = 1/8

#define BQ 8              // queries per CTA (small -> 2 CTAs/SM)
#define BK 128            // key tile
#define NTHREADS 256
#define LIST_CAP 192

// smem layout (float indices):
//   S     : [8][2048]        = 16384
//   Ks    : [128][64] swz    =  8192   (float4 col = d4 ^ (row&7))
//   Qs    : [8][64]          =   512
//   klist : [8][LIST_CAP]    =  1536 (ints)
//   wlist : [8][LIST_CAP]    =  1536
#define S_OFF   0
#define KS_OFF  16384
#define QS_OFF  (KS_OFF + BK*64)            // 24576
#define KL_OFF  (QS_OFF + BQ*64)            // 25088
#define WL_OFF  (KL_OFF + 8*LIST_CAP)       // 26624
#define SMEM_FLOATS (WL_OFF + 8*LIST_CAP)   // 28160
#define SMEM_BYTES  (SMEM_FLOATS * 4)       // 112640  -> 2 CTAs/SM

extern __shared__ float smem[];

__device__ __forceinline__ float warp_max(float x) {
    #pragma unroll
    for (int o = 16; o; o >>= 1) x = fmaxf(x, __shfl_xor_sync(0xffffffffu, x, o));
    return x;
}
__device__ __forceinline__ float warp_min(float x) {
    #pragma unroll
    for (int o = 16; o; o >>= 1) x = fminf(x, __shfl_xor_sync(0xffffffffu, x, o));
    return x;
}
__device__ __forceinline__ float warp_sum(float x) {
    #pragma unroll
    for (int o = 16; o; o >>= 1) x += __shfl_xor_sync(0xffffffffu, x, o);
    return x;
}

__global__ __launch_bounds__(NTHREADS, 2)
void topk_attn_kernel(const float* __restrict__ Q,
                      const float* __restrict__ K,
                      const float* __restrict__ V,
                      float* __restrict__ Out) {
    const int bh  = blockIdx.y;
    const int q0  = blockIdx.x * BQ;
    const int tid = threadIdx.x;
    const int lane = tid & 31;
    const int wid  = tid >> 5;

    float* S    = smem + S_OFF;
    float4* Ks4 = (float4*)(smem + KS_OFF);
    float4* Qs4 = (float4*)(smem + QS_OFF);
    int*   klist = (int*)(smem + KL_OFF);
    float* wlist = smem + WL_OFF;

    const size_t base = (size_t)bh * L_DIM * D_DIM;
    const float4* Q4 = (const float4*)(Q + base);
    const float4* K4 = (const float4*)(K + base);

    // ---- load Q tile (8 rows x 16 float4), plain layout (reads are broadcast) ----
    if (tid < BQ * 16) {
        int r = tid >> 4, c = tid & 15;
        Qs4[r * 16 + c] = Q4[(q0 + r) * 16 + c];
    }

    const int nk = q0 + BQ;                 // keys needed: 0..nk-1
    const int ntiles = (nk + BK - 1) / BK;

    // phase-1 thread mapping: warp w -> q rows {qh, qh+4}, key half kh
    const int qh = wid >> 1;                // 0..3
    const int kh = wid & 1;                 // 0..1
    const int kb = lane + 32 * kh;          // key base within tile (r&7 == lane&7)

    // ================= Phase 1: S = Q @ K^T (fp32, swizzled smem) =================
    for (int tile = 0; tile < ntiles; tile++) {
        const int k0 = tile * BK;
        __syncthreads();   // prior tile consumed before overwriting Ks
        // load K tile: 128 rows x 16 float4, XOR-swizzled store
        #pragma unroll
        for (int i = 0; i < 8; i++) {
            int idx = i * 256 + tid;
            int r = idx >> 4, c = idx & 15;
            Ks4[r * 16 + (c ^ (r & 7))] = K4[(k0 + r) * 16 + c];
        }
        __syncthreads();

        float acc00 = 0.f, acc01 = 0.f, acc10 = 0.f, acc11 = 0.f;
        const int r0 = kb, r1 = kb + 64;
        const int sw = lane & 7;
        #pragma unroll
        for (int d4 = 0; d4 < 16; d4++) {
            float4 k0v = Ks4[r0 * 16 + (d4 ^ sw)];
            float4 k1v = Ks4[r1 * 16 + (d4 ^ sw)];
            float4 q0v = Qs4[qh * 16 + d4];
            float4 q1v = Qs4[(qh + 4) * 16 + d4];
            acc00 = fmaf(q0v.x, k0v.x, acc00); acc00 = fmaf(q0v.y, k0v.y, acc00);
            acc00 = fmaf(q0v.z, k0v.z, acc00); acc00 = fmaf(q0v.w, k0v.w, acc00);
            acc01 = fmaf(q0v.x, k1v.x, acc01); acc01 = fmaf(q0v.y, k1v.y, acc01);
            acc01 = fmaf(q0v.z, k1v.z, acc01); acc01 = fmaf(q0v.w, k1v.w, acc01);
            acc10 = fmaf(q1v.x, k0v.x, acc10); acc10 = fmaf(q1v.y, k0v.y, acc10);
            acc10 = fmaf(q1v.z, k0v.z, acc10); acc10 = fmaf(q1v.w, k0v.w, acc10);
            acc11 = fmaf(q1v.x, k1v.x, acc11); acc11 = fmaf(q1v.y, k1v.y, acc11);
            acc11 = fmaf(q1v.z, k1v.z, acc11); acc11 = fmaf(q1v.w, k1v.w, acc11);
        }
        S[ qh      * 2048 + k0 + r0] = acc00;
        S[ qh      * 2048 + k0 + r1] = acc01;
        S[(qh + 4) * 2048 + k0 + r0] = acc10;
        S[(qh + 4) * 2048 + k0 + r1] = acc11;
    }
    __syncthreads();

    // ================= Phase 2: per-warp top-k threshold =================
    const unsigned FULL = 0xffffffffu;
    const unsigned lt = (1u << lane) - 1u;
    const int qi = wid;                     // one query per warp
    const int q  = q0 + qi;
    const int n  = q + 1;                   // valid keys

    float v[64];
    float mx = -FLT_MAX, mn = FLT_MAX;
    #pragma unroll
    for (int j = 0; j < 64; j++) {
        int k = 32 * j + lane;
        float val = -FLT_MAX;
        if (k < n) {
            val = S[qi * 2048 + k];
            mn = fminf(mn, val);
        }
        v[j] = val;
        mx = fmaxf(mx, val);
    }
    mx = warp_max(mx);
    mn = warp_min(mn);

    float t = -FLT_MAX;
    if (n > TOPK) {
        float lo = mn, hi = mx + 1.0f;
        #pragma unroll 1
        for (int it = 0; it < 48; it++) {
            float mid = 0.5f * (lo + hi);
            if (mid <= lo || mid >= hi) break;
            int c = 0;
            #pragma unroll
            for (int j = 0; j < 64; j++) c += (v[j] >= mid) ? 1 : 0;
            c = __reduce_add_sync(FULL, c);
            if (c == TOPK) { lo = mid; break; }
            if (c > TOPK) lo = mid; else hi = mid;
        }
        t = lo;
    }

    // compact selected (k, w) into per-warp smem list, accumulate Z
    int*   kl = klist + wid * LIST_CAP;
    float* wl = wlist + wid * LIST_CAP;
    float zsum = 0.f;
    int bpos = 0;
    #pragma unroll
    for (int j = 0; j < 64; j++) {
        int k = 32 * j + lane;
        bool sel = (k < n) && (v[j] >= t);
        unsigned m = __ballot_sync(FULL, sel);
        if (sel) {
            float w = __expf(SCALE * (v[j] - mx));
            zsum += w;
            int pos = bpos + __popc(m & lt);
            if (pos < LIST_CAP) { kl[pos] = k; wl[pos] = w; }
        }
        bpos += __popc(m);
    }
    int cnt = min(bpos, LIST_CAP);
    float Z = warp_sum(zsum);
    __syncwarp();

    // ================= Phase 3: gather V (float2, 8-deep MLP) =================
    const float2* Vb2 = (const float2*)(V + base);
    float2* Ob2 = (float2*)(Out + base);

    float ax = 0.f, ay = 0.f;
    int i = 0;
    #pragma unroll 1
    for (; i + 8 <= cnt; i += 8) {
        int   kk[8];
        float ww[8];
        float2 xv[8];
        #pragma unroll
        for (int u = 0; u < 8; u++) { kk[u] = kl[i + u]; ww[u] = wl[i + u]; }
        #pragma unroll
        for (int u = 0; u < 8; u++) xv[u] = Vb2[kk[u] * 32 + lane];
        #pragma unroll
        for (int u = 0; u < 8; u++) {
            ax = fmaf(ww[u], xv[u].x, ax);
            ay = fmaf(ww[u], xv[u].y, ay);
        }
    }
    #pragma unroll 1
    for (; i < cnt; i++) {
        int kk = kl[i]; float w = wl[i];
        float2 xv = Vb2[kk * 32 + lane];
        ax = fmaf(w, xv.x, ax);
        ay = fmaf(w, xv.y, ay);
    }

    float inv = 1.0f / Z;
    float2 o; o.x = ax * inv; o.y = ay * inv;
    Ob2[q * 32 + lane] = o;
}

extern "C" void kernel_launch(void* const* d_in, const int* in_sizes, int n_in,
                              void* d_out, int out_size) {
    const float* Q = (const float*)d_in[0];
    const float* K = (const float*)d_in[1];
    const float* V = (const float*)d_in[2];
    float* O = (float*)d_out;

    cudaFuncSetAttribute(topk_attn_kernel,
                         cudaFuncAttributeMaxDynamicSharedMemorySize, SMEM_BYTES);
    dim3 grid(L_DIM / BQ, B_DIM * H_DIM);
    topk_attn_kernel<<<grid, NTHREADS, SMEM_BYTES>>>(Q, K, V, O);
}

// round 4
// speedup vs baseline: 1.4807x; 1.4807x over previous
#include <cuda_runtime.h>
#include <float.h>

// Problem constants (fixed shapes per reference)
#define B_DIM 4
#define H_DIM 16
#define L_DIM 2048
#define D_DIM 64
#define TOPK  128
#define SCALE 0.125f      // D^-0.5 = 1/8

#define BQ 16             // queries per CTA
#define BK 128            // key tile (register-prefetched)
#define NTHREADS 256
#define LIST_CAP 192

// smem layout (float indices):
//   S     : [16][2048]       = 32768   (131072 B)
//   Ks    : [128][64] swz    =  8192   (float4 col = d4 ^ (row&7))
//   Qs    : [16][64]         =  1024
//   klist : [8][LIST_CAP]    =  1536 (ints)
//   wlist : [8][LIST_CAP]    =  1536
#define S_OFF   0
#define KS_OFF  32768
#define QS_OFF  (KS_OFF + BK*64)            // 40960
#define KL_OFF  (QS_OFF + BQ*64)            // 41984
#define WL_OFF  (KL_OFF + 8*LIST_CAP)       // 43520
#define SMEM_FLOATS (WL_OFF + 8*LIST_CAP)   // 45056
#define SMEM_BYTES  (SMEM_FLOATS * 4)       // 180224 -> 1 CTA/SM

extern __shared__ float smem[];

__device__ __forceinline__ float warp_max(float x) {
    #pragma unroll
    for (int o = 16; o; o >>= 1) x = fmaxf(x, __shfl_xor_sync(0xffffffffu, x, o));
    return x;
}
__device__ __forceinline__ float warp_min(float x) {
    #pragma unroll
    for (int o = 16; o; o >>= 1) x = fminf(x, __shfl_xor_sync(0xffffffffu, x, o));
    return x;
}
__device__ __forceinline__ float warp_sum(float x) {
    #pragma unroll
    for (int o = 16; o; o >>= 1) x += __shfl_xor_sync(0xffffffffu, x, o);
    return x;
}

__global__ __launch_bounds__(NTHREADS, 1)
void topk_attn_kernel(const float* __restrict__ Q,
                      const float* __restrict__ K,
                      const float* __restrict__ V,
                      float* __restrict__ Out) {
    const int bh  = blockIdx.y;
    const int q0  = blockIdx.x * BQ;
    const int tid = threadIdx.x;
    const int lane = tid & 31;
    const int wid  = tid >> 5;

    float* S    = smem + S_OFF;
    float4* Ks4 = (float4*)(smem + KS_OFF);
    float4* Qs4 = (float4*)(smem + QS_OFF);
    int*   klist = (int*)(smem + KL_OFF);
    float* wlist = smem + WL_OFF;

    const size_t base = (size_t)bh * L_DIM * D_DIM;
    const float4* Q4 = (const float4*)(Q + base);
    const float4* K4 = (const float4*)(K + base);

    // ---- load Q tile (16 rows x 16 float4), plain layout (reads broadcast) ----
    {
        int r = tid >> 4, c = tid & 15;
        Qs4[r * 16 + c] = Q4[(q0 + r) * 16 + c];
    }

    const int nk = q0 + BQ;                 // keys needed: 0..nk-1
    const int ntiles = (nk + BK - 1) / BK;

    // phase-1 mapping: thread -> q rows {qg, qg+4, qg+8, qg+12}, keys {kc, kc+64}
    const int qg = tid >> 6;                // 0..3
    const int kc = tid & 63;                // 0..63
    const int sw = kc & 7;                  // swizzle for K reads (kc&7 == (kc+64)&7)

    // K prefetch mapping: 8 float4/thread, rows row_base+16i, col c
    const int row_base = tid >> 4;          // 0..15
    const int cql = tid & 15;               // 0..15
    const int cs  = cql ^ (row_base & 7);   // swizzled store column (constant)

    // preload tile 0 into registers
    float4 pf[8];
    #pragma unroll
    for (int i = 0; i < 8; i++)
        pf[i] = K4[(row_base + 16 * i) * 16 + cql];

    // ================= Phase 1: S = Q @ K^T (fp32, pipelined) =================
    for (int tile = 0; tile < ntiles; tile++) {
        __syncthreads();   // prior tile fully consumed before overwrite
        #pragma unroll
        for (int i = 0; i < 8; i++)
            Ks4[(row_base + 16 * i) * 16 + cs] = pf[i];
        if (tile + 1 < ntiles) {
            const int k0n = (tile + 1) * BK;
            #pragma unroll
            for (int i = 0; i < 8; i++)
                pf[i] = K4[(k0n + row_base + 16 * i) * 16 + cql];
        }
        __syncthreads();

        float acc[4][2];
        #pragma unroll
        for (int i = 0; i < 4; i++) { acc[i][0] = 0.f; acc[i][1] = 0.f; }

        #pragma unroll
        for (int d4 = 0; d4 < 16; d4++) {
            float4 k0v = Ks4[ kc       * 16 + (d4 ^ sw)];
            float4 k1v = Ks4[(kc + 64) * 16 + (d4 ^ sw)];
            #pragma unroll
            for (int i = 0; i < 4; i++) {
                float4 qv = Qs4[(qg + 4 * i) * 16 + d4];
                acc[i][0] = fmaf(qv.x, k0v.x, acc[i][0]);
                acc[i][0] = fmaf(qv.y, k0v.y, acc[i][0]);
                acc[i][0] = fmaf(qv.z, k0v.z, acc[i][0]);
                acc[i][0] = fmaf(qv.w, k0v.w, acc[i][0]);
                acc[i][1] = fmaf(qv.x, k1v.x, acc[i][1]);
                acc[i][1] = fmaf(qv.y, k1v.y, acc[i][1]);
                acc[i][1] = fmaf(qv.z, k1v.z, acc[i][1]);
                acc[i][1] = fmaf(qv.w, k1v.w, acc[i][1]);
            }
        }
        const int k0 = tile * BK;
        #pragma unroll
        for (int i = 0; i < 4; i++) {
            S[(qg + 4 * i) * 2048 + k0 + kc]      = acc[i][0];
            S[(qg + 4 * i) * 2048 + k0 + kc + 64] = acc[i][1];
        }
    }
    __syncthreads();

    // ============ Phase 2+3: per-warp top-k select + V gather ============
    const unsigned FULL = 0xffffffffu;
    const unsigned lt = (1u << lane) - 1u;
    const float2* Vb2 = (const float2*)(V + base);
    float2* Ob2 = (float2*)(Out + base);
    const int p0 = wid & 1;   // stagger: odd warps do their 2nd query first

    #pragma unroll 1
    for (int pp = 0; pp < 2; pp++) {
        const int pass = pp ^ p0;
        const int qi = wid + 8 * pass;
        const int q  = q0 + qi;
        const int n  = q + 1;               // valid keys

        // load row into registers (64 per lane), track max & min of valid
        float v[64];
        float mx = -FLT_MAX, mn = FLT_MAX;
        #pragma unroll
        for (int j = 0; j < 64; j++) {
            int k = 32 * j + lane;
            float val = -FLT_MAX;
            if (k < n) {
                val = S[qi * 2048 + k];
                mn = fminf(mn, val);
            }
            v[j] = val;
            mx = fmaxf(mx, val);
        }
        mx = warp_max(mx);
        mn = warp_min(mn);

        // threshold: count(v >= t) == TOPK
        float t = -FLT_MAX;
        if (n > TOPK) {
            float lo = mn, hi = mx + 1.0f;
            #pragma unroll 1
            for (int it = 0; it < 48; it++) {
                float mid = 0.5f * (lo + hi);
                if (mid <= lo || mid >= hi) break;
                int c = 0;
                #pragma unroll
                for (int j = 0; j < 64; j++) c += (v[j] >= mid) ? 1 : 0;
                c = __reduce_add_sync(FULL, c);
                if (c == TOPK) { lo = mid; break; }
                if (c > TOPK) lo = mid; else hi = mid;
            }
            t = lo;
        }

        // compact selected (k, w) into per-warp smem list, accumulate Z
        int*   kl = klist + wid * LIST_CAP;
        float* wl = wlist + wid * LIST_CAP;
        float zsum = 0.f;
        int bpos = 0;
        #pragma unroll
        for (int j = 0; j < 64; j++) {
            int k = 32 * j + lane;
            bool sel = (k < n) && (v[j] >= t);
            unsigned m = __ballot_sync(FULL, sel);
            if (sel) {
                float w = __expf(SCALE * (v[j] - mx));
                zsum += w;
                int pos = bpos + __popc(m & lt);
                if (pos < LIST_CAP) { kl[pos] = k; wl[pos] = w; }
            }
            bpos += __popc(m);
        }
        int cnt = min(bpos, LIST_CAP);
        float Z = warp_sum(zsum);
        __syncwarp();

        // gather V rows (L2-resident) and accumulate, 8-deep MLP
        float ax = 0.f, ay = 0.f;
        int i = 0;
        #pragma unroll 1
        for (; i + 8 <= cnt; i += 8) {
            int   kk[8];
            float ww[8];
            float2 xv[8];
            #pragma unroll
            for (int u = 0; u < 8; u++) { kk[u] = kl[i + u]; ww[u] = wl[i + u]; }
            #pragma unroll
            for (int u = 0; u < 8; u++) xv[u] = Vb2[kk[u] * 32 + lane];
            #pragma unroll
            for (int u = 0; u < 8; u++) {
                ax = fmaf(ww[u], xv[u].x, ax);
                ay = fmaf(ww[u], xv[u].y, ay);
            }
        }
        #pragma unroll 1
        for (; i < cnt; i++) {
            int kk = kl[i]; float w = wl[i];
            float2 xv = Vb2[kk * 32 + lane];
            ax = fmaf(w, xv.x, ax);
            ay = fmaf(w, xv.y, ay);
        }

        float inv = 1.0f / Z;
        float2 o; o.x = ax * inv; o.y = ay * inv;
        Ob2[q * 32 + lane] = o;
    }
}

extern "C" void kernel_launch(void* const* d_in, const int* in_sizes, int n_in,
                              void* d_out, int out_size) {
    const float* Q = (const float*)d_in[0];
    const float* K = (const float*)d_in[1];
    const float* V = (const float*)d_in[2];
    float* O = (float*)d_out;

    cudaFuncSetAttribute(topk_attn_kernel,
                         cudaFuncAttributeMaxDynamicSharedMemorySize, SMEM_BYTES);
    dim3 grid(L_DIM / BQ, B_DIM * H_DIM);
    topk_attn_kernel<<<grid, NTHREADS, SMEM_BYTES>>>(Q, K, V, O);
}

// round 6
// speedup vs baseline: 1.7417x; 1.1763x over previous
#include <cuda_runtime.h>
#include <float.h>

// Problem constants (fixed shapes per reference)
#define B_DIM 4
#define H_DIM 16
#define L_DIM 2048
#define D_DIM 64
#define TOPK  128
#define SCALE 0.125f      // D^-0.5 = 1/8

#define BQ 16             // queries per CTA
#define BK 256            // key tile (register-prefetched)
#define NTHREADS 512
#define NWARPS 16
#define LIST_CAP 192

// smem layout (float indices):
//   S     : [16][2048]       = 32768   (131072 B)
//   Ks    : [256][64] swz    = 16384   (float4 col = c ^ (row&7))
//   Qs    : [16][64]         =  1024
//   klist : [16][LIST_CAP]   =  3072 (ints)
//   wlist : [16][LIST_CAP]   =  3072
#define S_OFF   0
#define KS_OFF  32768
#define QS_OFF  (KS_OFF + BK*64)                 // 49152
#define KL_OFF  (QS_OFF + BQ*64)                 // 50176
#define WL_OFF  (KL_OFF + NWARPS*LIST_CAP)       // 53248
#define SMEM_FLOATS (WL_OFF + NWARPS*LIST_CAP)   // 56320
#define SMEM_BYTES  (SMEM_FLOATS * 4)            // 225280 -> 1 CTA/SM

extern __shared__ float smem[];

__device__ __forceinline__ float warp_max(float x) {
    #pragma unroll
    for (int o = 16; o; o >>= 1) x = fmaxf(x, __shfl_xor_sync(0xffffffffu, x, o));
    return x;
}
__device__ __forceinline__ float warp_min(float x) {
    #pragma unroll
    for (int o = 16; o; o >>= 1) x = fminf(x, __shfl_xor_sync(0xffffffffu, x, o));
    return x;
}
__device__ __forceinline__ float warp_sum(float x) {
    #pragma unroll
    for (int o = 16; o; o >>= 1) x += __shfl_xor_sync(0xffffffffu, x, o);
    return x;
}

__global__ __launch_bounds__(NTHREADS, 1)
void topk_attn_kernel(const float* __restrict__ Q,
                      const float* __restrict__ K,
                      const float* __restrict__ V,
                      float* __restrict__ Out) {
    const int bh  = blockIdx.y;
    const int q0  = blockIdx.x * BQ;
    const int tid = threadIdx.x;
    const int lane = tid & 31;
    const int wid  = tid >> 5;

    float* S    = smem + S_OFF;
    float4* Ks4 = (float4*)(smem + KS_OFF);
    float4* Qs4 = (float4*)(smem + QS_OFF);
    int*   klist = (int*)(smem + KL_OFF);
    float* wlist = smem + WL_OFF;

    const size_t base = (size_t)bh * L_DIM * D_DIM;
    const float4* Q4 = (const float4*)(Q + base);
    const float4* K4 = (const float4*)(K + base);

    // ---- load Q tile (16 rows x 16 float4), plain layout (reads broadcast) ----
    if (tid < BQ * 16) {
        int r = tid >> 4, c = tid & 15;
        Qs4[r * 16 + c] = Q4[(q0 + r) * 16 + c];
    }

    const int nk = q0 + BQ;                 // keys needed: 0..nk-1
    const int ntiles = (nk + BK - 1) / BK;

    // phase-1 mapping: thread -> q rows {qg,qg+4,qg+8,qg+12}, keys {kc, kc+128}
    const int qg = tid >> 7;                // 0..3
    const int kc = tid & 127;               // 0..127
    const int sw = kc & 7;                  // (kc+128)&7 == kc&7 -> same swizzle

    // K prefetch mapping: 8 float4/thread, rows row_base+32i, col cql
    const int row_base = tid >> 4;          // 0..31
    const int cql = tid & 15;               // 0..15
    const int cs  = cql ^ (row_base & 7);   // swizzled store column (constant)

    // preload tile 0 into registers
    float4 pf[8];
    #pragma unroll
    for (int i = 0; i < 8; i++)
        pf[i] = K4[(row_base + 32 * i) * 16 + cql];

    // ================= Phase 1: S = Q @ K^T (fp32, pipelined) =================
    for (int tile = 0; tile < ntiles; tile++) {
        __syncthreads();   // prior tile fully consumed before overwrite
        #pragma unroll
        for (int i = 0; i < 8; i++)
            Ks4[(row_base + 32 * i) * 16 + cs] = pf[i];
        if (tile + 1 < ntiles) {
            const int k0n = (tile + 1) * BK;
            #pragma unroll
            for (int i = 0; i < 8; i++)
                pf[i] = K4[(k0n + row_base + 32 * i) * 16 + cql];
        }
        __syncthreads();

        float acc[4][2];
        #pragma unroll
        for (int i = 0; i < 4; i++) { acc[i][0] = 0.f; acc[i][1] = 0.f; }

        #pragma unroll
        for (int d4 = 0; d4 < 16; d4++) {
            float4 k0v = Ks4[ kc        * 16 + (d4 ^ sw)];
            float4 k1v = Ks4[(kc + 128) * 16 + (d4 ^ sw)];
            #pragma unroll
            for (int i = 0; i < 4; i++) {
                float4 qv = Qs4[(qg + 4 * i) * 16 + d4];
                acc[i][0] = fmaf(qv.x, k0v.x, acc[i][0]);
                acc[i][0] = fmaf(qv.y, k0v.y, acc[i][0]);
                acc[i][0] = fmaf(qv.z, k0v.z, acc[i][0]);
                acc[i][0] = fmaf(qv.w, k0v.w, acc[i][0]);
                acc[i][1] = fmaf(qv.x, k1v.x, acc[i][1]);
                acc[i][1] = fmaf(qv.y, k1v.y, acc[i][1]);
                acc[i][1] = fmaf(qv.z, k1v.z, acc[i][1]);
                acc[i][1] = fmaf(qv.w, k1v.w, acc[i][1]);
            }
        }
        const int k0 = tile * BK;
        #pragma unroll
        for (int i = 0; i < 4; i++) {
            S[(qg + 4 * i) * 2048 + k0 + kc]       = acc[i][0];
            S[(qg + 4 * i) * 2048 + k0 + kc + 128] = acc[i][1];
        }
    }
    __syncthreads();

    // ============ Phase 2+3: one query per warp: top-k select + V gather ============
    const unsigned FULL = 0xffffffffu;
    const unsigned lt = (1u << lane) - 1u;
    const float2* Vb2 = (const float2*)(V + base);
    float2* Ob2 = (float2*)(Out + base);

    const int qi = wid;                     // one query per warp
    const int q  = q0 + qi;
    const int n  = q + 1;                   // valid keys

    // load row into registers (64 per lane), track max & min of valid
    float v[64];
    float mx = -FLT_MAX, mn = FLT_MAX;
    #pragma unroll
    for (int j = 0; j < 64; j++) {
        int k = 32 * j + lane;
        float val = -FLT_MAX;
        if (k < n) {
            val = S[qi * 2048 + k];
            mn = fminf(mn, val);
        }
        v[j] = val;
        mx = fmaxf(mx, val);
    }
    mx = warp_max(mx);
    mn = warp_min(mn);

    // threshold: count(v >= t) == TOPK
    float t = -FLT_MAX;
    if (n > TOPK) {
        float lo = mn, hi = mx + 1.0f;
        #pragma unroll 1
        for (int it = 0; it < 48; it++) {
            float mid = 0.5f * (lo + hi);
            if (mid <= lo || mid >= hi) break;
            int c = 0;
            #pragma unroll
            for (int j = 0; j < 64; j++) c += (v[j] >= mid) ? 1 : 0;
            c = __reduce_add_sync(FULL, c);
            if (c == TOPK) { lo = mid; break; }
            if (c > TOPK) lo = mid; else hi = mid;
        }
        t = lo;
    }

    // compact selected (k, w) into per-warp smem list, accumulate Z
    int*   kl = klist + wid * LIST_CAP;
    float* wl = wlist + wid * LIST_CAP;
    float zsum = 0.f;
    int bpos = 0;
    #pragma unroll
    for (int j = 0; j < 64; j++) {
        int k = 32 * j + lane;
        bool sel = (k < n) && (v[j] >= t);
        unsigned m = __ballot_sync(FULL, sel);
        if (sel) {
            float w = __expf(SCALE * (v[j] - mx));
            zsum += w;
            int pos = bpos + __popc(m & lt);
            if (pos < LIST_CAP) { kl[pos] = k; wl[pos] = w; }
        }
        bpos += __popc(m);
    }
    int cnt = min(bpos, LIST_CAP);
    float Z = warp_sum(zsum);
    __syncwarp();

    // gather V rows (L2-resident) and accumulate, 8-deep MLP
    float ax = 0.f, ay = 0.f;
    int i = 0;
    #pragma unroll 1
    for (; i + 8 <= cnt; i += 8) {
        int   kk[8];
        float ww[8];
        float2 xv[8];
        #pragma unroll
        for (int u = 0; u < 8; u++) { kk[u] = kl[i + u]; ww[u] = wl[i + u]; }
        #pragma unroll
        for (int u = 0; u < 8; u++) xv[u] = Vb2[kk[u] * 32 + lane];
        #pragma unroll
        for (int u = 0; u < 8; u++) {
            ax = fmaf(ww[u], xv[u].x, ax);
            ay = fmaf(ww[u], xv[u].y, ay);
        }
    }
    #pragma unroll 1
    for (; i < cnt; i++) {
        int kk = kl[i]; float w = wl[i];
        float2 xv = Vb2[kk * 32 + lane];
        ax = fmaf(w, xv.x, ax);
        ay = fmaf(w, xv.y, ay);
    }

    float inv = 1.0f / Z;
    float2 o; o.x = ax * inv; o.y = ay * inv;
    Ob2[q * 32 + lane] = o;
}

extern "C" void kernel_launch(void* const* d_in, const int* in_sizes, int n_in,
                              void* d_out, int out_size) {
    const float* Q = (const float*)d_in[0];
    const float* K = (const float*)d_in[1];
    const float* V = (const float*)d_in[2];
    float* O = (float*)d_out;

    cudaFuncSetAttribute(topk_attn_kernel,
                         cudaFuncAttributeMaxDynamicSharedMemorySize, SMEM_BYTES);
    dim3 grid(L_DIM / BQ, B_DIM * H_DIM);
    topk_attn_kernel<<<grid, NTHREADS, SMEM_BYTES>>>(Q, K, V, O);
}

// round 10
// speedup vs baseline: 2.0635x; 1.1847x over previous
#include <cuda_runtime.h>
#include <cuda_bf16.h>
#include <float.h>
#include <stdint.h>

// Problem constants
#define B_DIM 4
#define H_DIM 16
#define L_DIM 2048
#define D_DIM 64
#define TOPK  128
#define SCALE 0.125f

#define BQ 16
#define BK 128            // keys per tile (8 key-groups x 16 keys; 2 query-groups)
#define NTHREADS 512
#define NWARPS 16
#define LIST_CAP 192
#define S_STRIDE 2052     // padded: conflict-free MMA scatter + phase-2 reads

// dynamic smem byte offsets
#define S_OFF      0                       // float[16][2052]          131328
#define KH_OFF     131328                  // K hi  bf16 [128][128B]    16384
#define KM_OFF     147712                  // K mid bf16                16384
#define KL_OFF     164096                  // K lo  bf16                16384
#define QH_OFF     180480                  // Q hi  bf16 [16][128B]      2048
#define QM_OFF     182528                  // Q mid                      2048
#define QL_OFF     184576                  // Q lo                       2048
#define KLIST_OFF  186624                  // int[16][192]              12288
#define WLIST_OFF  198912                  // float[16][192]            12288
#define SMEM_BYTES 211200                  // < 227 KB cap

extern __shared__ char smem_raw[];

// ---------------- PTX helpers (baseline ISA only) ----------------
__device__ __forceinline__ uint32_t smem_u32(const void* p) {
    uint32_t a;
    asm("{ .reg .u64 t; cvta.to.shared.u64 t, %1; cvt.u32.u64 %0, t; }" : "=r"(a) : "l"(p));
    return a;
}
__device__ __forceinline__ void ldsm4(uint32_t* r, uint32_t addr) {
    asm volatile("ldmatrix.sync.aligned.m8n8.x4.shared.b16 {%0,%1,%2,%3}, [%4];"
                 : "=r"(r[0]), "=r"(r[1]), "=r"(r[2]), "=r"(r[3]) : "r"(addr));
}
// non-trans x2: B fragment from n-major (query-major) tile
__device__ __forceinline__ void ldsm2(uint32_t* r, uint32_t addr) {
    asm volatile("ldmatrix.sync.aligned.m8n8.x2.shared.b16 {%0,%1}, [%2];"
                 : "=r"(r[0]), "=r"(r[1]) : "r"(addr));
}
__device__ __forceinline__ void mma_bf16(float* d, const uint32_t* a, const uint32_t* b) {
    asm volatile("mma.sync.aligned.m16n8k16.row.col.f32.bf16.bf16.f32 "
                 "{%0,%1,%2,%3}, {%4,%5,%6,%7}, {%8,%9}, {%0,%1,%2,%3};"
                 : "+f"(d[0]), "+f"(d[1]), "+f"(d[2]), "+f"(d[3])
                 : "r"(a[0]), "r"(a[1]), "r"(a[2]), "r"(a[3]), "r"(b[0]), "r"(b[1]));
}

__device__ __forceinline__ float warp_max(float x) {
    #pragma unroll
    for (int o = 16; o; o >>= 1) x = fmaxf(x, __shfl_xor_sync(0xffffffffu, x, o));
    return x;
}
__device__ __forceinline__ float warp_min(float x) {
    #pragma unroll
    for (int o = 16; o; o >>= 1) x = fminf(x, __shfl_xor_sync(0xffffffffu, x, o));
    return x;
}
__device__ __forceinline__ float warp_sum(float x) {
    #pragma unroll
    for (int o = 16; o; o >>= 1) x += __shfl_xor_sync(0xffffffffu, x, o);
    return x;
}

// 3-way split: f = hi + mid + lo (each bf16); residual <= 2^-27 |f|
__device__ __forceinline__ void cvt_store3(char* b0, char* b1, char* b2,
                                           int row, int c, float4 f) {
    __nv_bfloat162 h01 = __float22bfloat162_rn(make_float2(f.x, f.y));
    __nv_bfloat162 h23 = __float22bfloat162_rn(make_float2(f.z, f.w));
    float2 g01 = __bfloat1622float2(h01);
    float2 g23 = __bfloat1622float2(h23);
    float4 r1 = make_float4(f.x - g01.x, f.y - g01.y, f.z - g23.x, f.w - g23.y);
    __nv_bfloat162 m01 = __float22bfloat162_rn(make_float2(r1.x, r1.y));
    __nv_bfloat162 m23 = __float22bfloat162_rn(make_float2(r1.z, r1.w));
    float2 p01 = __bfloat1622float2(m01);
    float2 p23 = __bfloat1622float2(m23);
    __nv_bfloat162 l01 = __float22bfloat162_rn(make_float2(r1.x - p01.x, r1.y - p01.y));
    __nv_bfloat162 l23 = __float22bfloat162_rn(make_float2(r1.z - p23.x, r1.w - p23.y));
    int off = row * 128 + c * 8;
    int sw  = off ^ ((row & 7) << 4);
    uint2 hv, mv, lv;
    hv.x = *reinterpret_cast<uint32_t*>(&h01);
    hv.y = *reinterpret_cast<uint32_t*>(&h23);
    mv.x = *reinterpret_cast<uint32_t*>(&m01);
    mv.y = *reinterpret_cast<uint32_t*>(&m23);
    lv.x = *reinterpret_cast<uint32_t*>(&l01);
    lv.y = *reinterpret_cast<uint32_t*>(&l23);
    *reinterpret_cast<uint2*>(b0 + sw) = hv;
    *reinterpret_cast<uint2*>(b1 + sw) = mv;
    *reinterpret_cast<uint2*>(b2 + sw) = lv;
}

__global__ __launch_bounds__(NTHREADS, 1)
void topk_attn_kernel(const float* __restrict__ Q,
                      const float* __restrict__ K,
                      const float* __restrict__ V,
                      float* __restrict__ Out) {
    const int bh  = blockIdx.y;
    const int q0  = blockIdx.x * BQ;
    const int tid = threadIdx.x;
    const int lane = tid & 31;
    const int wid  = tid >> 5;

    float* Sf    = (float*)(smem_raw + S_OFF);
    int*   klist = (int*)(smem_raw + KLIST_OFF);
    float* wlist = (float*)(smem_raw + WLIST_OFF);
    const uint32_t smem_base = smem_u32(smem_raw);

    const size_t base = (size_t)bh * L_DIM * D_DIM;
    const float4* Q4 = (const float4*)(Q + base);
    const float4* K4 = (const float4*)(K + base);

    // ---- convert Q tile (16 rows x 16 float4) to bf16 hi/mid/lo ----
    if (tid < 256) {
        int r = tid >> 4, c = tid & 15;
        float4 f = Q4[(q0 + r) * 16 + c];
        cvt_store3(smem_raw + QH_OFF, smem_raw + QM_OFF, smem_raw + QL_OFF, r, c, f);
    }

    const int nk = q0 + BQ;
    const int ntiles = (nk + BK - 1) / BK;

    // K prefetch: 4 float4/thread, idx = i*512+tid -> row=idx>>4 (0..127), c=idx&15
    float4 pf[4];
    #pragma unroll
    for (int i = 0; i < 4; i++) {
        int idx = i * 512 + tid;
        pf[i] = K4[(idx >> 4) * 16 + (idx & 15)];
    }
    __syncthreads();   // Q tiles visible

    // ---- persistent Q fragments: this warp's query group h = wid>>3 ----
    const int hgrp = wid >> 3;             // 0 or 1 (queries hgrp*8 .. +7)
    uint32_t qh[4][2], qm[4][2], ql[4][2];
    {
        int l   = lane & 15;
        int row = l & 7;
        int cb  = (l >> 3) * 16;           // matrix select within kstep
        int r   = hgrp * 8 + row;
        #pragma unroll
        for (int ks = 0; ks < 4; ks++) {
            uint32_t off = (uint32_t)((ks * 32 + cb) ^ (row << 4));
            ldsm2(qh[ks], smem_base + QH_OFF + r * 128 + off);
            ldsm2(qm[ks], smem_base + QM_OFF + r * 128 + off);
            ldsm2(ql[ks], smem_base + QL_OFF + r * 128 + off);
        }
    }

    // A-fragment addressing: key group = wid&7 (16 keys)
    const int kloc = (wid & 7) * 16;
    const int g  = lane >> 3;
    const int ri = lane & 7;
    const int arow = kloc + ri + (g & 1) * 8;
    const int acol0 = (g >> 1) * 16;
    const uint32_t aswz = (uint32_t)(ri << 4);

    // ============ Phase 1: S^T = K @ Q^T via mma.sync (3-way bf16 split) ============
    for (int tile = 0; tile < ntiles; tile++) {
        const int kbase = tile * BK + kloc;
        __syncthreads();   // prior tile fully consumed before overwrite
        #pragma unroll
        for (int i = 0; i < 4; i++) {
            int idx = i * 512 + tid;
            cvt_store3(smem_raw + KH_OFF, smem_raw + KM_OFF, smem_raw + KL_OFF,
                       idx >> 4, idx & 15, pf[i]);
        }
        if (tile + 1 < ntiles) {
            const int r0 = (tile + 1) * BK;
            #pragma unroll
            for (int i = 0; i < 4; i++) {
                int idx = i * 512 + tid;
                pf[i] = K4[(r0 + (idx >> 4)) * 16 + (idx & 15)];
            }
        }
        __syncthreads();

        if (kbase < nk) {
            float d[4] = {0.f, 0.f, 0.f, 0.f};
            #pragma unroll
            for (int ks = 0; ks < 4; ks++) {
                uint32_t ah[4], am[4], al[4];
                uint32_t coff = (uint32_t)((ks * 32 + acol0) ^ aswz);
                ldsm4(ah, smem_base + KH_OFF + arow * 128 + coff);
                ldsm4(am, smem_base + KM_OFF + arow * 128 + coff);
                ldsm4(al, smem_base + KL_OFF + arow * 128 + coff);
                mma_bf16(d, al, qh[ks]);   // lh (~2^-18)
                mma_bf16(d, ah, ql[ks]);   // hl (~2^-18)
                mma_bf16(d, am, qm[ks]);   // mm (~2^-18)
                mma_bf16(d, am, qh[ks]);   // mh (~2^-9)
                mma_bf16(d, ah, qm[ks]);   // hm (~2^-9)
                mma_bf16(d, ah, qh[ks]);   // hh
            }
            // store D (16 keys x 8 queries) transposed into S
            const int r = lane >> 2, c = (lane & 3) * 2;
            const int key = kbase + r;
            const int qq = hgrp * 8 + c;
            Sf[ qq      * S_STRIDE + key]     = d[0];
            Sf[(qq + 1) * S_STRIDE + key]     = d[1];
            Sf[ qq      * S_STRIDE + key + 8] = d[2];
            Sf[(qq + 1) * S_STRIDE + key + 8] = d[3];
        }
    }
    __syncthreads();

    // ============ Phase 2: one query per warp: top-k threshold ============
    const unsigned FULL = 0xffffffffu;
    const unsigned lt = (1u << lane) - 1u;
    const int qi = wid;
    const int q  = q0 + qi;
    const int n  = q + 1;

    float v[64];
    float mx = -FLT_MAX, mn = FLT_MAX;
    #pragma unroll
    for (int jb = 0; jb < 4; jb++) {
        if (jb * 512 < n) {
            #pragma unroll
            for (int jj = 0; jj < 16; jj++) {
                int j = jb * 16 + jj;
                int k = 32 * j + lane;
                float val = -FLT_MAX;
                if (k < n) {
                    val = Sf[qi * S_STRIDE + k];
                    mn = fminf(mn, val);
                }
                v[j] = val;
                mx = fmaxf(mx, val);
            }
        }
    }
    mx = warp_max(mx);
    mn = warp_min(mn);

    float t = -FLT_MAX;
    if (n > TOPK) {
        float lo = mn, hi = mx;
        float clo = (float)n, chi = 1.0f;
        #pragma unroll 1
        for (int it = 0; it < 40; it++) {
            float mid;
            if ((it & 3) == 3) mid = 0.5f * (lo + hi);
            else               mid = lo + (hi - lo) * ((clo - (float)TOPK) / fmaxf(clo - chi, 1.0f));
            if (!(mid > lo && mid < hi)) mid = 0.5f * (lo + hi);
            if (mid <= lo || mid >= hi) break;
            int c = 0;
            #pragma unroll
            for (int jb = 0; jb < 4; jb++) {
                if (jb * 512 < n) {
                    #pragma unroll
                    for (int jj = 0; jj < 16; jj++) c += (v[jb * 16 + jj] >= mid) ? 1 : 0;
                }
            }
            c = __reduce_add_sync(FULL, c);
            if (c == TOPK) { lo = mid; break; }
            if (c > TOPK) { lo = mid; clo = (float)c; }
            else          { hi = mid; chi = (float)c; }
        }
        t = lo;
    }

    // compact selected (k, w) into per-warp smem list, accumulate Z
    int*   kl = klist + wid * LIST_CAP;
    float* wl = wlist + wid * LIST_CAP;
    float zsum = 0.f;
    int bpos = 0;
    #pragma unroll
    for (int jb = 0; jb < 4; jb++) {
        if (jb * 512 < n) {
            #pragma unroll
            for (int jj = 0; jj < 16; jj++) {
                int j = jb * 16 + jj;
                int k = 32 * j + lane;
                bool sel = (k < n) && (v[j] >= t);
                unsigned m = __ballot_sync(FULL, sel);
                if (sel) {
                    float w = __expf(SCALE * (v[j] - mx));
                    zsum += w;
                    int pos = bpos + __popc(m & lt);
                    if (pos < LIST_CAP) { kl[pos] = k; wl[pos] = w; }
                }
                bpos += __popc(m);
            }
        }
    }
    int cnt = min(bpos, LIST_CAP);
    float Z = warp_sum(zsum);
    __syncwarp();

    // ============ Phase 3: gather V (float2, 8-deep MLP) ============
    const float2* Vb2 = (const float2*)(V + base);
    float2* Ob2 = (float2*)(Out + base);

    float ax = 0.f, ay = 0.f;
    int i = 0;
    #pragma unroll 1
    for (; i + 8 <= cnt; i += 8) {
        int   kk[8];
        float ww[8];
        float2 xv[8];
        #pragma unroll
        for (int u = 0; u < 8; u++) { kk[u] = kl[i + u]; ww[u] = wl[i + u]; }
        #pragma unroll
        for (int u = 0; u < 8; u++) xv[u] = Vb2[kk[u] * 32 + lane];
        #pragma unroll
        for (int u = 0; u < 8; u++) {
            ax = fmaf(ww[u], xv[u].x, ax);
            ay = fmaf(ww[u], xv[u].y, ay);
        }
    }
    #pragma unroll 1
    for (; i < cnt; i++) {
        int kk = kl[i]; float w = wl[i];
        float2 xv = Vb2[kk * 32 + lane];
        ax = fmaf(w, xv.x, ax);
        ay = fmaf(w, xv.y, ay);
    }

    float inv = 1.0f / Z;
    float2 o; o.x = ax * inv; o.y = ay * inv;
    Ob2[q * 32 + lane] = o;
}

extern "C" void kernel_launch(void* const* d_in, const int* in_sizes, int n_in,
                              void* d_out, int out_size) {
    const float* Q = (const float*)d_in[0];
    const float* K = (const float*)d_in[1];
    const float* V = (const float*)d_in[2];
    float* O = (float*)d_out;

    cudaFuncSetAttribute(topk_attn_kernel,
                         cudaFuncAttributeMaxDynamicSharedMemorySize, SMEM_BYTES);
    dim3 grid(L_DIM / BQ, B_DIM * H_DIM);
    topk_attn_kernel<<<grid, NTHREADS, SMEM_BYTES>>>(Q, K, V, O);
}

// round 11
// speedup vs baseline: 2.1779x; 1.0555x over previous
#include <cuda_runtime.h>
#include <cuda_bf16.h>
#include <float.h>
#include <stdint.h>

// Problem constants
#define B_DIM 4
#define H_DIM 16
#define L_DIM 2048
#define D_DIM 64
#define TOPK  128
#define SCALE 0.125f

#define BQ 16
#define BK 128            // keys per tile (8 key-groups x 16 keys; 2 query-groups)
#define NTHREADS 512
#define NWARPS 16
#define LIST_CAP 192
#define S_STRIDE 2052     // padded: conflict-free MMA scatter + phase-2 reads

#define KTOT (B_DIM*H_DIM*L_DIM*D_DIM)    // 8,388,608 elements

// Precomputed 3-way bf16 split of K (hi/mid/lo), row-major [bh][l][d].
// uint4 granularity (8 bf16 per uint4), 16MB each.
__device__ uint4 Kh_g[KTOT/8];
__device__ uint4 Km_g[KTOT/8];
__device__ uint4 Kl_g[KTOT/8];

// dynamic smem byte offsets
#define S_OFF      0                       // float[16][2052]          131328
#define KH_OFF     131328                  // K hi  bf16 [128][128B]    16384
#define KM_OFF     147712                  // K mid bf16                16384
#define KL_OFF     164096                  // K lo  bf16                16384
#define QH_OFF     180480                  // Q hi  bf16 [16][128B]      2048
#define QM_OFF     182528                  // Q mid                      2048
#define QL_OFF     184576                  // Q lo                       2048
#define KLIST_OFF  186624                  // int[16][192]              12288
#define WLIST_OFF  198912                  // float[16][192]            12288
#define SMEM_BYTES 211200                  // < 227 KB cap

extern __shared__ char smem_raw[];

// ---------------- PTX helpers (baseline ISA only) ----------------
__device__ __forceinline__ uint32_t smem_u32(const void* p) {
    uint32_t a;
    asm("{ .reg .u64 t; cvta.to.shared.u64 t, %1; cvt.u32.u64 %0, t; }" : "=r"(a) : "l"(p));
    return a;
}
__device__ __forceinline__ void ldsm4(uint32_t* r, uint32_t addr) {
    asm volatile("ldmatrix.sync.aligned.m8n8.x4.shared.b16 {%0,%1,%2,%3}, [%4];"
                 : "=r"(r[0]), "=r"(r[1]), "=r"(r[2]), "=r"(r[3]) : "r"(addr));
}
// non-trans x2: B fragment from n-major (query-major) tile
__device__ __forceinline__ void ldsm2(uint32_t* r, uint32_t addr) {
    asm volatile("ldmatrix.sync.aligned.m8n8.x2.shared.b16 {%0,%1}, [%2];"
                 : "=r"(r[0]), "=r"(r[1]) : "r"(addr));
}
__device__ __forceinline__ void mma_bf16(float* d, const uint32_t* a, const uint32_t* b) {
    asm volatile("mma.sync.aligned.m16n8k16.row.col.f32.bf16.bf16.f32 "
                 "{%0,%1,%2,%3}, {%4,%5,%6,%7}, {%8,%9}, {%0,%1,%2,%3};"
                 : "+f"(d[0]), "+f"(d[1]), "+f"(d[2]), "+f"(d[3])
                 : "r"(a[0]), "r"(a[1]), "r"(a[2]), "r"(a[3]), "r"(b[0]), "r"(b[1]));
}

__device__ __forceinline__ float warp_max(float x) {
    #pragma unroll
    for (int o = 16; o; o >>= 1) x = fmaxf(x, __shfl_xor_sync(0xffffffffu, x, o));
    return x;
}
__device__ __forceinline__ float warp_min(float x) {
    #pragma unroll
    for (int o = 16; o; o >>= 1) x = fminf(x, __shfl_xor_sync(0xffffffffu, x, o));
    return x;
}
__device__ __forceinline__ float warp_sum(float x) {
    #pragma unroll
    for (int o = 16; o; o >>= 1) x += __shfl_xor_sync(0xffffffffu, x, o);
    return x;
}

// split f into hi+mid+lo bf16 pairs (packed)
__device__ __forceinline__ void split3(float4 f, uint2& hv, uint2& mv, uint2& lv) {
    __nv_bfloat162 h01 = __float22bfloat162_rn(make_float2(f.x, f.y));
    __nv_bfloat162 h23 = __float22bfloat162_rn(make_float2(f.z, f.w));
    float2 g01 = __bfloat1622float2(h01);
    float2 g23 = __bfloat1622float2(h23);
    float4 r1 = make_float4(f.x - g01.x, f.y - g01.y, f.z - g23.x, f.w - g23.y);
    __nv_bfloat162 m01 = __float22bfloat162_rn(make_float2(r1.x, r1.y));
    __nv_bfloat162 m23 = __float22bfloat162_rn(make_float2(r1.z, r1.w));
    float2 p01 = __bfloat1622float2(m01);
    float2 p23 = __bfloat1622float2(m23);
    __nv_bfloat162 l01 = __float22bfloat162_rn(make_float2(r1.x - p01.x, r1.y - p01.y));
    __nv_bfloat162 l23 = __float22bfloat162_rn(make_float2(r1.z - p23.x, r1.w - p23.y));
    hv.x = *reinterpret_cast<uint32_t*>(&h01);
    hv.y = *reinterpret_cast<uint32_t*>(&h23);
    mv.x = *reinterpret_cast<uint32_t*>(&m01);
    mv.y = *reinterpret_cast<uint32_t*>(&m23);
    lv.x = *reinterpret_cast<uint32_t*>(&l01);
    lv.y = *reinterpret_cast<uint32_t*>(&l23);
}

// store split to swizzled smem tile (8B granularity)
__device__ __forceinline__ void cvt_store3(char* b0, char* b1, char* b2,
                                           int row, int c, float4 f) {
    uint2 hv, mv, lv;
    split3(f, hv, mv, lv);
    int off = row * 128 + c * 8;
    int sw  = off ^ ((row & 7) << 4);
    *reinterpret_cast<uint2*>(b0 + sw) = hv;
    *reinterpret_cast<uint2*>(b1 + sw) = mv;
    *reinterpret_cast<uint2*>(b2 + sw) = lv;
}

// ============ prep kernel: split K into 3 bf16 planes (global) ============
__global__ __launch_bounds__(256, 4)
void prep_split_kernel(const float* __restrict__ K) {
    int idx = blockIdx.x * 256 + threadIdx.x;        // float4 index, 0..KTOT/4-1
    float4 f = ((const float4*)K)[idx];
    uint2 hv, mv, lv;
    split3(f, hv, mv, lv);
    ((uint2*)Kh_g)[idx] = hv;
    ((uint2*)Km_g)[idx] = mv;
    ((uint2*)Kl_g)[idx] = lv;
}

__global__ __launch_bounds__(NTHREADS, 1)
void topk_attn_kernel(const float* __restrict__ Q,
                      const float* __restrict__ V,
                      float* __restrict__ Out) {
    const int bh  = blockIdx.y;
    const int q0  = blockIdx.x * BQ;
    const int tid = threadIdx.x;
    const int lane = tid & 31;
    const int wid  = tid >> 5;

    float* Sf    = (float*)(smem_raw + S_OFF);
    int*   klist = (int*)(smem_raw + KLIST_OFF);
    float* wlist = (float*)(smem_raw + WLIST_OFF);
    const uint32_t smem_base = smem_u32(smem_raw);

    const size_t base = (size_t)bh * L_DIM * D_DIM;
    const float4* Q4 = (const float4*)(Q + base);
    const uint4* KH4 = Kh_g + (base >> 3);
    const uint4* KM4 = Km_g + (base >> 3);
    const uint4* KL4 = Kl_g + (base >> 3);

    // ---- convert Q tile (16 rows x 16 float4) to bf16 hi/mid/lo ----
    if (tid < 256) {
        int r = tid >> 4, c = tid & 15;
        float4 f = Q4[(q0 + r) * 16 + c];
        cvt_store3(smem_raw + QH_OFF, smem_raw + QM_OFF, smem_raw + QL_OFF, r, c, f);
    }

    const int nk = q0 + BQ;
    const int ntiles = (nk + BK - 1) / BK;

    // K tile prefetch: 2 uint4/thread/plane. idx=i*512+tid -> row=idx>>3, c16=idx&7
    uint4 ph[2], pm[2], pl[2];
    #pragma unroll
    for (int i = 0; i < 2; i++) {
        int idx = i * 512 + tid;
        ph[i] = KH4[idx];
        pm[i] = KM4[idx];
        pl[i] = KL4[idx];
    }
    __syncthreads();   // Q tiles visible

    // ---- persistent Q fragments: this warp's query group h = wid>>3 ----
    const int hgrp = wid >> 3;             // 0 or 1 (queries hgrp*8 .. +7)
    uint32_t qh[4][2], qm[4][2], ql[4][2];
    {
        int l   = lane & 15;
        int row = l & 7;
        int cb  = (l >> 3) * 16;           // matrix select within kstep
        int r   = hgrp * 8 + row;
        #pragma unroll
        for (int ks = 0; ks < 4; ks++) {
            uint32_t off = (uint32_t)((ks * 32 + cb) ^ (row << 4));
            ldsm2(qh[ks], smem_base + QH_OFF + r * 128 + off);
            ldsm2(qm[ks], smem_base + QM_OFF + r * 128 + off);
            ldsm2(ql[ks], smem_base + QL_OFF + r * 128 + off);
        }
    }

    // A-fragment addressing: key group = wid&7 (16 keys)
    const int kloc = (wid & 7) * 16;
    const int g  = lane >> 3;
    const int ri = lane & 7;
    const int arow = kloc + ri + (g & 1) * 8;
    const int acol0 = (g >> 1) * 16;
    const uint32_t aswz = (uint32_t)(ri << 4);

    // ============ Phase 1: S^T = K @ Q^T via mma.sync (3-way bf16 split) ============
    for (int tile = 0; tile < ntiles; tile++) {
        const int kbase = tile * BK + kloc;
        __syncthreads();   // prior tile fully consumed before overwrite
        #pragma unroll
        for (int i = 0; i < 2; i++) {
            int idx = i * 512 + tid;
            int row = idx >> 3, c = idx & 7;
            int sw = row * 128 + ((c * 16) ^ ((row & 7) << 4));
            *reinterpret_cast<uint4*>(smem_raw + KH_OFF + sw) = ph[i];
            *reinterpret_cast<uint4*>(smem_raw + KM_OFF + sw) = pm[i];
            *reinterpret_cast<uint4*>(smem_raw + KL_OFF + sw) = pl[i];
        }
        if (tile + 1 < ntiles) {
            const int b0 = (tile + 1) * 1024;
            #pragma unroll
            for (int i = 0; i < 2; i++) {
                int idx = b0 + i * 512 + tid;
                ph[i] = KH4[idx];
                pm[i] = KM4[idx];
                pl[i] = KL4[idx];
            }
        }
        __syncthreads();

        if (kbase < nk) {
            float d[4] = {0.f, 0.f, 0.f, 0.f};
            #pragma unroll
            for (int ks = 0; ks < 4; ks++) {
                uint32_t ah[4], am[4], al[4];
                uint32_t coff = (uint32_t)((ks * 32 + acol0) ^ aswz);
                ldsm4(ah, smem_base + KH_OFF + arow * 128 + coff);
                ldsm4(am, smem_base + KM_OFF + arow * 128 + coff);
                ldsm4(al, smem_base + KL_OFF + arow * 128 + coff);
                mma_bf16(d, al, qh[ks]);   // lh
                mma_bf16(d, ah, ql[ks]);   // hl
                mma_bf16(d, am, qm[ks]);   // mm
                mma_bf16(d, am, qh[ks]);   // mh
                mma_bf16(d, ah, qm[ks]);   // hm
                mma_bf16(d, ah, qh[ks]);   // hh
            }
            // store D (16 keys x 8 queries) transposed into S
            const int r = lane >> 2, c = (lane & 3) * 2;
            const int key = kbase + r;
            const int qq = hgrp * 8 + c;
            Sf[ qq      * S_STRIDE + key]     = d[0];
            Sf[(qq + 1) * S_STRIDE + key]     = d[1];
            Sf[ qq      * S_STRIDE + key + 8] = d[2];
            Sf[(qq + 1) * S_STRIDE + key + 8] = d[3];
        }
    }
    __syncthreads();

    // ============ Phase 2: one query per warp: top-k threshold ============
    const unsigned FULL = 0xffffffffu;
    const unsigned lt = (1u << lane) - 1u;
    const int qi = wid;
    const int q  = q0 + qi;
    const int n  = q + 1;

    float v[64];
    float mx = -FLT_MAX, mn = FLT_MAX;
    #pragma unroll
    for (int jb = 0; jb < 4; jb++) {
        if (jb * 512 < n) {
            #pragma unroll
            for (int jj = 0; jj < 16; jj++) {
                int j = jb * 16 + jj;
                int k = 32 * j + lane;
                float val = -FLT_MAX;
                if (k < n) {
                    val = Sf[qi * S_STRIDE + k];
                    mn = fminf(mn, val);
                }
                v[j] = val;
                mx = fmaxf(mx, val);
            }
        }
    }
    mx = warp_max(mx);
    mn = warp_min(mn);

    float t = -FLT_MAX;
    if (n > TOPK) {
        float lo = mn, hi = mx;
        float clo = (float)n, chi = 1.0f;
        #pragma unroll 1
        for (int it = 0; it < 40; it++) {
            float mid;
            if ((it & 3) == 3) mid = 0.5f * (lo + hi);
            else               mid = lo + (hi - lo) * ((clo - (float)TOPK) / fmaxf(clo - chi, 1.0f));
            if (!(mid > lo && mid < hi)) mid = 0.5f * (lo + hi);
            if (mid <= lo || mid >= hi) break;
            int c = 0;
            #pragma unroll
            for (int jb = 0; jb < 4; jb++) {
                if (jb * 512 < n) {
                    #pragma unroll
                    for (int jj = 0; jj < 16; jj++) c += (v[jb * 16 + jj] >= mid) ? 1 : 0;
                }
            }
            c = __reduce_add_sync(FULL, c);
            if (c == TOPK) { lo = mid; break; }
            if (c > TOPK) { lo = mid; clo = (float)c; }
            else          { hi = mid; chi = (float)c; }
        }
        t = lo;
    }

    // compact selected (k, w) into per-warp smem list, accumulate Z
    int*   kl = klist + wid * LIST_CAP;
    float* wl = wlist + wid * LIST_CAP;
    float zsum = 0.f;
    int bpos = 0;
    #pragma unroll
    for (int jb = 0; jb < 4; jb++) {
        if (jb * 512 < n) {
            #pragma unroll
            for (int jj = 0; jj < 16; jj++) {
                int j = jb * 16 + jj;
                int k = 32 * j + lane;
                bool sel = (k < n) && (v[j] >= t);
                unsigned m = __ballot_sync(FULL, sel);
                if (sel) {
                    float w = __expf(SCALE * (v[j] - mx));
                    zsum += w;
                    int pos = bpos + __popc(m & lt);
                    if (pos < LIST_CAP) { kl[pos] = k; wl[pos] = w; }
                }
                bpos += __popc(m);
            }
        }
    }
    int cnt = min(bpos, LIST_CAP);
    float Z = warp_sum(zsum);
    __syncwarp();

    // ============ Phase 3: gather V (float2, 16-deep MLP) ============
    const float2* Vb2 = (const float2*)(V + base);
    float2* Ob2 = (float2*)(Out + base);

    float ax = 0.f, ay = 0.f;
    int i = 0;
    #pragma unroll 1
    for (; i + 16 <= cnt; i += 16) {
        int   kk[16];
        float ww[16];
        float2 xv[16];
        #pragma unroll
        for (int u = 0; u < 16; u++) { kk[u] = kl[i + u]; ww[u] = wl[i + u]; }
        #pragma unroll
        for (int u = 0; u < 16; u++) xv[u] = Vb2[kk[u] * 32 + lane];
        #pragma unroll
        for (int u = 0; u < 16; u++) {
            ax = fmaf(ww[u], xv[u].x, ax);
            ay = fmaf(ww[u], xv[u].y, ay);
        }
    }
    #pragma unroll 1
    for (; i < cnt; i++) {
        int kk = kl[i]; float w = wl[i];
        float2 xv = Vb2[kk * 32 + lane];
        ax = fmaf(w, xv.x, ax);
        ay = fmaf(w, xv.y, ay);
    }

    float inv = 1.0f / Z;
    float2 o; o.x = ax * inv; o.y = ay * inv;
    Ob2[q * 32 + lane] = o;
}

extern "C" void kernel_launch(void* const* d_in, const int* in_sizes, int n_in,
                              void* d_out, int out_size) {
    const float* Q = (const float*)d_in[0];
    const float* K = (const float*)d_in[1];
    const float* V = (const float*)d_in[2];
    float* O = (float*)d_out;

    // 1) split K into bf16 hi/mid/lo planes
    prep_split_kernel<<<KTOT / 4 / 256, 256>>>(K);

    // 2) main fused kernel
    cudaFuncSetAttribute(topk_attn_kernel,
                         cudaFuncAttributeMaxDynamicSharedMemorySize, SMEM_BYTES);
    dim3 grid(L_DIM / BQ, B_DIM * H_DIM);
    topk_attn_kernel<<<grid, NTHREADS, SMEM_BYTES>>>(Q, V, O);
}

// round 12
// speedup vs baseline: 2.5729x; 1.1813x over previous
#include <cuda_runtime.h>
#include <cuda_bf16.h>
#include <float.h>
#include <stdint.h>

// Problem constants
#define B_DIM 4
#define H_DIM 16
#define L_DIM 2048
#define D_DIM 64
#define TOPK  128
#define SCALE 0.125f
#define NBH   (B_DIM*H_DIM)
#define KTOT  (NBH*L_DIM*D_DIM)          // 8,388,608
#define LIST_CAP 192

// ---- global scratch (sanctioned __device__ arrays) ----
__device__ uint4 Kh_g[KTOT/8];           // 16 MB each: 3-way bf16 planes
__device__ uint4 Km_g[KTOT/8];
__device__ uint4 Kl_g[KTOT/8];
__device__ uint4 Qh_g[KTOT/8];
__device__ uint4 Qm_g[KTOT/8];
__device__ uint4 Ql_g[KTOT/8];
__device__ float S_g[(size_t)NBH * L_DIM * L_DIM];   // 1 GB score matrix

// ---------------- PTX helpers (baseline ISA only) ----------------
__device__ __forceinline__ uint32_t smem_u32(const void* p) {
    uint32_t a;
    asm("{ .reg .u64 t; cvta.to.shared.u64 t, %1; cvt.u32.u64 %0, t; }" : "=r"(a) : "l"(p));
    return a;
}
__device__ __forceinline__ void ldsm4(uint32_t* r, uint32_t addr) {
    asm volatile("ldmatrix.sync.aligned.m8n8.x4.shared.b16 {%0,%1,%2,%3}, [%4];"
                 : "=r"(r[0]), "=r"(r[1]), "=r"(r[2]), "=r"(r[3]) : "r"(addr));
}
__device__ __forceinline__ void mma_bf16(float* d, const uint32_t* a, const uint32_t* b) {
    asm volatile("mma.sync.aligned.m16n8k16.row.col.f32.bf16.bf16.f32 "
                 "{%0,%1,%2,%3}, {%4,%5,%6,%7}, {%8,%9}, {%0,%1,%2,%3};"
                 : "+f"(d[0]), "+f"(d[1]), "+f"(d[2]), "+f"(d[3])
                 : "r"(a[0]), "r"(a[1]), "r"(a[2]), "r"(a[3]), "r"(b[0]), "r"(b[1]));
}
__device__ __forceinline__ float warp_max(float x) {
    #pragma unroll
    for (int o = 16; o; o >>= 1) x = fmaxf(x, __shfl_xor_sync(0xffffffffu, x, o));
    return x;
}
__device__ __forceinline__ float warp_min(float x) {
    #pragma unroll
    for (int o = 16; o; o >>= 1) x = fminf(x, __shfl_xor_sync(0xffffffffu, x, o));
    return x;
}
__device__ __forceinline__ float warp_sum(float x) {
    #pragma unroll
    for (int o = 16; o; o >>= 1) x += __shfl_xor_sync(0xffffffffu, x, o);
    return x;
}

// split f into hi+mid+lo bf16 pairs (packed)
__device__ __forceinline__ void split3(float4 f, uint2& hv, uint2& mv, uint2& lv) {
    __nv_bfloat162 h01 = __float22bfloat162_rn(make_float2(f.x, f.y));
    __nv_bfloat162 h23 = __float22bfloat162_rn(make_float2(f.z, f.w));
    float2 g01 = __bfloat1622float2(h01);
    float2 g23 = __bfloat1622float2(h23);
    float4 r1 = make_float4(f.x - g01.x, f.y - g01.y, f.z - g23.x, f.w - g23.y);
    __nv_bfloat162 m01 = __float22bfloat162_rn(make_float2(r1.x, r1.y));
    __nv_bfloat162 m23 = __float22bfloat162_rn(make_float2(r1.z, r1.w));
    float2 p01 = __bfloat1622float2(m01);
    float2 p23 = __bfloat1622float2(m23);
    __nv_bfloat162 l01 = __float22bfloat162_rn(make_float2(r1.x - p01.x, r1.y - p01.y));
    __nv_bfloat162 l23 = __float22bfloat162_rn(make_float2(r1.z - p23.x, r1.w - p23.y));
    hv.x = *reinterpret_cast<uint32_t*>(&h01);
    hv.y = *reinterpret_cast<uint32_t*>(&h23);
    mv.x = *reinterpret_cast<uint32_t*>(&m01);
    mv.y = *reinterpret_cast<uint32_t*>(&m23);
    lv.x = *reinterpret_cast<uint32_t*>(&l01);
    lv.y = *reinterpret_cast<uint32_t*>(&l23);
}

// ============ kernel 1: split Q and K into 3 bf16 planes ============
__global__ __launch_bounds__(256, 4)
void prep_split_kernel(const float* __restrict__ Q, const float* __restrict__ K) {
    int idx = blockIdx.x * 256 + threadIdx.x;        // float4 index
    uint2 hv, mv, lv;
    float4 f = ((const float4*)K)[idx];
    split3(f, hv, mv, lv);
    ((uint2*)Kh_g)[idx] = hv; ((uint2*)Km_g)[idx] = mv; ((uint2*)Kl_g)[idx] = lv;
    f = ((const float4*)Q)[idx];
    split3(f, hv, mv, lv);
    ((uint2*)Qh_g)[idx] = hv; ((uint2*)Qm_g)[idx] = mv; ((uint2*)Ql_g)[idx] = lv;
}

// ============ kernel 2: S = Q @ K^T (causal blocks only) ============
// grid: (136 lower-tri 128x128 block pairs, 64 bh). 512 threads.
// smem: Q planes 3x16KB + K planes 3x16KB = 96 KB.
#define GQH 0
#define GQM 16384
#define GQL 32768
#define GKH 49152
#define GKM 65536
#define GKL 81920
#define GSMEM 98304

extern __shared__ char gsm[];

__global__ __launch_bounds__(512)
void qk_gemm_kernel() {
    const int bh  = blockIdx.y;
    const int idx = blockIdx.x;
    int qt = (int)((sqrtf(8.f * (float)idx + 1.f) - 1.f) * 0.5f);
    while ((qt + 1) * (qt + 2) / 2 <= idx) qt++;
    while (qt * (qt + 1) / 2 > idx) qt--;
    const int kt = idx - qt * (qt + 1) / 2;

    const int tid = threadIdx.x, lane = tid & 31, wid = tid >> 5;

    // load tiles (swizzled)
    const size_t qb = ((size_t)bh * L_DIM + qt * 128) * 8;   // uint4 row stride 8
    const size_t kb = ((size_t)bh * L_DIM + kt * 128) * 8;
    #pragma unroll
    for (int i = 0; i < 2; i++) {
        int x = i * 512 + tid;
        int row = x >> 3, c = x & 7;
        int sw = row * 128 + ((c * 16) ^ ((row & 7) << 4));
        *(uint4*)(gsm + GQH + sw) = Qh_g[qb + row * 8 + c];
        *(uint4*)(gsm + GQM + sw) = Qm_g[qb + row * 8 + c];
        *(uint4*)(gsm + GQL + sw) = Ql_g[qb + row * 8 + c];
        *(uint4*)(gsm + GKH + sw) = Kh_g[kb + row * 8 + c];
        *(uint4*)(gsm + GKM + sw) = Km_g[kb + row * 8 + c];
        *(uint4*)(gsm + GKL + sw) = Kl_g[kb + row * 8 + c];
    }
    __syncthreads();

    const uint32_t smb = smem_u32(gsm);
    const int wq = wid >> 2, wk = wid & 3;     // warp tile: 32q x 32k
    const int g  = lane >> 3, ri = lane & 7;
    const int amrow = wq * 32 + ri + (g & 1) * 8;            // + mt*16
    const int acol0 = (g >> 1) * 16;
    const uint32_t aswz = (uint32_t)(ri << 4);
    const int brow = wk * 32 + ((lane >> 4) << 3) + (lane & 7);  // + p*16
    const int bcol0 = ((lane >> 3) & 1) * 16;
    const uint32_t bswz = (uint32_t)((lane & 7) << 4);

    float d[2][4][4];
    #pragma unroll
    for (int mt = 0; mt < 2; mt++)
        #pragma unroll
        for (int nt = 0; nt < 4; nt++)
            #pragma unroll
            for (int r = 0; r < 4; r++) d[mt][nt][r] = 0.f;

    #pragma unroll
    for (int ks = 0; ks < 4; ks++) {
        uint32_t aH[2][4], aM[2][4], aL[2][4];
        #pragma unroll
        for (int mt = 0; mt < 2; mt++) {
            uint32_t ro = (uint32_t)((amrow + mt * 16) * 128) + ((ks * 32 + acol0) ^ aswz);
            ldsm4(aH[mt], smb + GQH + ro);
            ldsm4(aM[mt], smb + GQM + ro);
            ldsm4(aL[mt], smb + GQL + ro);
        }
        uint32_t bH[2][4], bM[2][4], bL[2][4];
        #pragma unroll
        for (int p = 0; p < 2; p++) {
            uint32_t ro = (uint32_t)((brow + p * 16) * 128) + ((ks * 32 + bcol0) ^ bswz);
            ldsm4(bH[p], smb + GKH + ro);
            ldsm4(bM[p], smb + GKM + ro);
            ldsm4(bL[p], smb + GKL + ro);
        }
        #pragma unroll
        for (int mt = 0; mt < 2; mt++)
            #pragma unroll
            for (int p = 0; p < 2; p++)
                #pragma unroll
                for (int s = 0; s < 2; s++) {
                    float* acc = d[mt][p * 2 + s];
                    const uint32_t* bh_ = &bH[p][s * 2];
                    const uint32_t* bm_ = &bM[p][s * 2];
                    const uint32_t* bl_ = &bL[p][s * 2];
                    mma_bf16(acc, aL[mt], bh_);   // lh
                    mma_bf16(acc, aH[mt], bl_);   // hl
                    mma_bf16(acc, aM[mt], bm_);   // mm
                    mma_bf16(acc, aM[mt], bh_);   // mh
                    mma_bf16(acc, aH[mt], bm_);   // hm
                    mma_bf16(acc, aH[mt], bh_);   // hh
                }
    }

    // store D to S_g
    #pragma unroll
    for (int mt = 0; mt < 2; mt++) {
        int qr = qt * 128 + wq * 32 + mt * 16 + (lane >> 2);
        #pragma unroll
        for (int nt = 0; nt < 4; nt++) {
            int kc = kt * 128 + wk * 32 + nt * 8 + 2 * (lane & 3);
            size_t o0 = ((size_t)bh * L_DIM + qr) * L_DIM + kc;
            float2 v0; v0.x = d[mt][nt][0]; v0.y = d[mt][nt][1];
            float2 v1; v1.x = d[mt][nt][2]; v1.y = d[mt][nt][3];
            *(float2*)(S_g + o0) = v0;
            *(float2*)(S_g + o0 + (size_t)8 * L_DIM) = v1;
        }
    }
}

// ============ kernel 3: per-query top-k select + PV ============
// 128 threads = 4 warps, 1 warp per query. grid: (512, 64).
__global__ __launch_bounds__(128)
void select_pv_kernel(const float* __restrict__ V, float* __restrict__ Out) {
    __shared__ int   klist[4][LIST_CAP];
    __shared__ float wlist[4][LIST_CAP];

    const int tid = threadIdx.x, lane = tid & 31, wid = tid >> 5;
    const int bh = blockIdx.y;
    const int q  = blockIdx.x * 4 + wid;
    const int n  = q + 1;
    const unsigned FULL = 0xffffffffu;
    const unsigned lt = (1u << lane) - 1u;

    const float4* S4 = (const float4*)(S_g + ((size_t)bh * L_DIM + q) * L_DIM);

    // load row: 16 coalesced float4 per lane, mask invalid to -FLT_MAX
    float4 v4[16];
    float mx = -FLT_MAX, mn = FLT_MAX;
    #pragma unroll
    for (int j = 0; j < 16; j++) {
        int k0 = j * 128 + lane * 4;
        if (j * 128 < n) {                      // warp-uniform guard
            float4 f = S4[j * 32 + lane];
            float4 gg;
            gg.x = (k0     < n) ? f.x : -FLT_MAX;
            gg.y = (k0 + 1 < n) ? f.y : -FLT_MAX;
            gg.z = (k0 + 2 < n) ? f.z : -FLT_MAX;
            gg.w = (k0 + 3 < n) ? f.w : -FLT_MAX;
            v4[j] = gg;
            mx = fmaxf(mx, fmaxf(fmaxf(gg.x, gg.y), fmaxf(gg.z, gg.w)));
            if (k0     < n) mn = fminf(mn, f.x);
            if (k0 + 1 < n) mn = fminf(mn, f.y);
            if (k0 + 2 < n) mn = fminf(mn, f.z);
            if (k0 + 3 < n) mn = fminf(mn, f.w);
        } else {
            v4[j] = make_float4(-FLT_MAX, -FLT_MAX, -FLT_MAX, -FLT_MAX);
        }
    }
    mx = warp_max(mx);
    mn = warp_min(mn);

    // threshold: count(v >= t) == TOPK (regula falsi + bisection safeguard)
    float t = -FLT_MAX;
    if (n > TOPK) {
        float lo = mn, hi = mx;
        float clo = (float)n, chi = 1.0f;
        #pragma unroll 1
        for (int it = 0; it < 40; it++) {
            float mid;
            if ((it & 3) == 3) mid = 0.5f * (lo + hi);
            else               mid = lo + (hi - lo) * ((clo - (float)TOPK) / fmaxf(clo - chi, 1.0f));
            if (!(mid > lo && mid < hi)) mid = 0.5f * (lo + hi);
            if (mid <= lo || mid >= hi) break;
            int c = 0;
            #pragma unroll
            for (int j = 0; j < 16; j++) {
                if (j * 128 < n) {
                    c += (v4[j].x >= mid) ? 1 : 0;
                    c += (v4[j].y >= mid) ? 1 : 0;
                    c += (v4[j].z >= mid) ? 1 : 0;
                    c += (v4[j].w >= mid) ? 1 : 0;
                }
            }
            c = __reduce_add_sync(FULL, c);
            if (c == TOPK) { lo = mid; break; }
            if (c > TOPK) { lo = mid; clo = (float)c; }
            else          { hi = mid; chi = (float)c; }
        }
        t = lo;
    }

    // compact selected (k, w), accumulate Z
    int*   kl = klist[wid];
    float* wl = wlist[wid];
    float zsum = 0.f;
    int bpos = 0;
    #pragma unroll
    for (int j = 0; j < 16; j++) {
        if (j * 128 < n) {
            float vals[4] = {v4[j].x, v4[j].y, v4[j].z, v4[j].w};
            #pragma unroll
            for (int cc = 0; cc < 4; cc++) {
                int k = j * 128 + lane * 4 + cc;
                bool sel = (k < n) && (vals[cc] >= t);
                unsigned m = __ballot_sync(FULL, sel);
                if (sel) {
                    float w = __expf(SCALE * (vals[cc] - mx));
                    zsum += w;
                    int pos = bpos + __popc(m & lt);
                    if (pos < LIST_CAP) { kl[pos] = k; wl[pos] = w; }
                }
                bpos += __popc(m);
            }
        }
    }
    int cnt = min(bpos, LIST_CAP);
    float Z = warp_sum(zsum);
    __syncwarp();

    // gather V (float2, 16-deep MLP)
    const float2* Vb2 = (const float2*)(V + (size_t)bh * L_DIM * D_DIM);
    float2* Ob2 = (float2*)(Out + (size_t)bh * L_DIM * D_DIM);

    float ax = 0.f, ay = 0.f;
    int i = 0;
    #pragma unroll 1
    for (; i + 16 <= cnt; i += 16) {
        int   kk[16];
        float ww[16];
        float2 xv[16];
        #pragma unroll
        for (int u = 0; u < 16; u++) { kk[u] = kl[i + u]; ww[u] = wl[i + u]; }
        #pragma unroll
        for (int u = 0; u < 16; u++) xv[u] = Vb2[kk[u] * 32 + lane];
        #pragma unroll
        for (int u = 0; u < 16; u++) {
            ax = fmaf(ww[u], xv[u].x, ax);
            ay = fmaf(ww[u], xv[u].y, ay);
        }
    }
    #pragma unroll 1
    for (; i < cnt; i++) {
        int kk = kl[i]; float w = wl[i];
        float2 xv = Vb2[kk * 32 + lane];
        ax = fmaf(w, xv.x, ax);
        ay = fmaf(w, xv.y, ay);
    }

    float inv = 1.0f / Z;
    float2 o; o.x = ax * inv; o.y = ay * inv;
    Ob2[q * 32 + lane] = o;
}

extern "C" void kernel_launch(void* const* d_in, const int* in_sizes, int n_in,
                              void* d_out, int out_size) {
    const float* Q = (const float*)d_in[0];
    const float* K = (const float*)d_in[1];
    const float* V = (const float*)d_in[2];
    float* O = (float*)d_out;

    // 1) split Q and K into bf16 hi/mid/lo planes
    prep_split_kernel<<<KTOT / 4 / 256, 256>>>(Q, K);

    // 2) causal-block GEMM into S_g
    cudaFuncSetAttribute(qk_gemm_kernel,
                         cudaFuncAttributeMaxDynamicSharedMemorySize, GSMEM);
    dim3 gg(136, NBH);
    qk_gemm_kernel<<<gg, 512, GSMEM>>>();

    // 3) per-query select + PV
    dim3 gs(L_DIM / 4, NBH);
    select_pv_kernel<<<gs, 128>>>(V, O);
}